// round 1
// baseline (speedup 1.0000x reference)
#include <cuda_runtime.h>
#include <cuda_bf16.h>

#define SPLIT 16
#define BPB   32          // bodies per block
#define EPSF  1e-9f

__global__ __launch_bounds__(512, 2)
void collide_kernel(const float* __restrict__ cpos,
                    const float* __restrict__ crad,
                    const float* __restrict__ apos,
                    const float* __restrict__ ahalf,
                    float* __restrict__ out,
                    int nc, int na, int cblocks)
{
    __shared__ float2 red[SPLIT][BPB];

    const int lane = threadIdx.x;   // body within block (0..31)
    const int s    = threadIdx.y;   // slice (0..15)

    float ax = 0.0f, ay = 0.0f;

    if ((int)blockIdx.x < cblocks) {
        // ---------------- circle blocks ----------------
        int i = blockIdx.x * BPB + lane;
        bool valid = (i < nc);
        int ii = valid ? i : 0;
        const float xi = cpos[2 * ii];
        const float yi = cpos[2 * ii + 1];
        const float ri = crad[ii];

        // circle vs circle
        #pragma unroll 4
        for (int j = s; j < nc; j += SPLIT) {
            float xj = cpos[2 * j], yj = cpos[2 * j + 1], rj = crad[j];
            float dx = xi - xj, dy = yi - yj;
            float d2 = fmaf(dx, dx, dy * dy);
            float rs = ri + rj;
            bool hit = (d2 > EPSF) & (d2 < rs * rs);
            float inv = rsqrtf(fmaxf(d2, EPSF));
            float f = hit ? fmaf(0.5f * rs, inv, -0.5f) : 0.0f;
            ax = fmaf(f, dx, ax);
            ay = fmaf(f, dy, ay);
        }

        // circle vs aabb (push on circle)
        #pragma unroll 4
        for (int a = s; a < na; a += SPLIT) {
            float xa = apos[2 * a], ya = apos[2 * a + 1];
            float hx = ahalf[2 * a], hy = ahalf[2 * a + 1];
            float rx = xi - xa, ry = yi - ya;
            float dx = rx - fminf(fmaxf(rx, -hx), hx);
            float dy = ry - fminf(fmaxf(ry, -hy), hy);
            float d2 = fmaf(dx, dx, dy * dy);
            bool hit = (d2 > EPSF) & (d2 < ri * ri);
            float inv = rsqrtf(fmaxf(d2, EPSF));
            float f = hit ? fmaf(0.5f * ri, inv, -0.5f) : 0.0f;
            ax = fmaf(f, dx, ax);
            ay = fmaf(f, dy, ay);
        }

        red[s][lane] = make_float2(ax, ay);
        __syncthreads();
        if (s == 0 && valid) {
            float sx = xi, sy = yi;
            #pragma unroll
            for (int t = 0; t < SPLIT; t++) {
                sx += red[t][lane].x;
                sy += red[t][lane].y;
            }
            out[2 * i] = sx;
            out[2 * i + 1] = sy;
        }
    } else {
        // ---------------- aabb blocks ----------------
        int b = (blockIdx.x - cblocks) * BPB + lane;
        bool valid = (b < na);
        int bb = valid ? b : 0;
        const float xb  = apos[2 * bb];
        const float yb  = apos[2 * bb + 1];
        const float hxb = ahalf[2 * bb];
        const float hyb = ahalf[2 * bb + 1];

        // aabb vs aabb
        #pragma unroll 4
        for (int k = s; k < na; k += SPLIT) {
            float xk = apos[2 * k], yk = apos[2 * k + 1];
            float hxk = ahalf[2 * k], hyk = ahalf[2 * k + 1];
            float dax = xb - xk, day = yb - yk;
            float ovx = hxb + hxk - fabsf(dax);
            float ovy = hyb + hyk - fabsf(day);
            bool hit = (k != bb) & (ovx > 0.0f) & (ovy > 0.0f);
            bool usex = (ovx <= ovy);
            float sgx = (dax >= 0.0f) ? 0.5f : -0.5f;
            float sgy = (day >= 0.0f) ? 0.5f : -0.5f;
            float px = usex ? ovx * sgx : 0.0f;
            float py = usex ? 0.0f : ovy * sgy;
            if (hit) { ax += px; ay += py; }
        }

        // circle vs aabb (equal-and-opposite push on box)
        #pragma unroll 4
        for (int j = s; j < nc; j += SPLIT) {
            float xj = cpos[2 * j], yj = cpos[2 * j + 1], rj = crad[j];
            float rx = xj - xb, ry = yj - yb;
            float dx = rx - fminf(fmaxf(rx, -hxb), hxb);
            float dy = ry - fminf(fmaxf(ry, -hyb), hyb);
            float d2 = fmaf(dx, dx, dy * dy);
            bool hit = (d2 > EPSF) & (d2 < rj * rj);
            float inv = rsqrtf(fmaxf(d2, EPSF));
            float f = hit ? fmaf(0.5f * rj, inv, -0.5f) : 0.0f;
            ax = fmaf(-f, dx, ax);
            ay = fmaf(-f, dy, ay);
        }

        red[s][lane] = make_float2(ax, ay);
        __syncthreads();
        if (s == 0 && valid) {
            float sx = xb, sy = yb;
            #pragma unroll
            for (int t = 0; t < SPLIT; t++) {
                sx += red[t][lane].x;
                sy += red[t][lane].y;
            }
            out[2 * (nc + b)] = sx;
            out[2 * (nc + b) + 1] = sy;
        }
    }
}

extern "C" void kernel_launch(void* const* d_in, const int* in_sizes, int n_in,
                              void* d_out, int out_size)
{
    const float* cpos  = (const float*)d_in[0];   // [nc,2]
    const float* crad  = (const float*)d_in[1];   // [nc]
    const float* apos  = (const float*)d_in[2];   // [na,2]
    const float* ahalf = (const float*)d_in[3];   // [na,2]
    float* out = (float*)d_out;                   // [nc+na, 2]

    int nc = in_sizes[1];          // element count of circle_radius
    int na = in_sizes[2] / 2;      // aabb_pos has na*2 elements

    int cblocks = (nc + BPB - 1) / BPB;
    int ablocks = (na + BPB - 1) / BPB;

    dim3 block(BPB, SPLIT);
    collide_kernel<<<cblocks + ablocks, block>>>(cpos, crad, apos, ahalf,
                                                 out, nc, na, cblocks);
}

// round 3
// speedup vs baseline: 1.6212x; 1.6212x over previous
#include <cuda_runtime.h>
#include <cuda_bf16.h>

#define EPSF 1e-9f
#define WPB  16              // warps per block (512 threads)
#define TARGET_WARPS 7104    // 148 SMs * 3 blocks * 16 warps

// partial sums: unit index (g*C + c) * 32 + lane  (float2 per lane)
__device__ float2 g_part[16384 * 32];

__global__ __launch_bounds__(512, 3)
void pairs_kernel(const float2* __restrict__ cpos,
                  const float*  __restrict__ crad,
                  const float2* __restrict__ apos,
                  const float2* __restrict__ ahalf,
                  int nc, int na, int gc, int ga, int C, int len)
{
    const int lane = threadIdx.x & 31;
    const int unit = blockIdx.x * WPB + (threadIdx.x >> 5);
    const int groups = gc + ga;
    if (unit >= groups * C) return;

    const int g = unit / C;
    const int c = unit - g * C;
    const int L = nc + na;                  // same inner length for both types
    const int lo = c * len;
    const int hi = min(L, lo + len);

    float ax = 0.0f, ay = 0.0f;

    if (g < gc) {
        // ------- circle body -------
        int i  = g * 32 + lane;
        int ii = min(i, nc - 1);
        const float2 p  = cpos[ii];
        const float rih = 0.5f * crad[ii];

        // circle vs circle over flattened idx [lo, min(hi,nc))
        int e1 = min(hi, nc);
        #pragma unroll 4
        for (int j = lo; j < e1; ++j) {
            float2 q = cpos[j];
            float rj = crad[j];
            float dx = p.x - q.x, dy = p.y - q.y;
            float d2 = fmaf(dx, dx, dy * dy);
            float rsh = fmaf(0.5f, rj, rih);
            float inv = rsqrtf(fmaxf(d2, EPSF));
            float f = fmaxf(fmaf(rsh, inv, -0.5f), 0.0f);
            f = (d2 > EPSF) ? f : 0.0f;
            ax = fmaf(f, dx, ax);
            ay = fmaf(f, dy, ay);
        }

        // circle vs aabb over flattened idx [max(lo,nc), hi)
        int s2 = max(lo, nc);
        #pragma unroll 4
        for (int idx = s2; idx < hi; ++idx) {
            int a = idx - nc;
            float2 q = apos[a];
            float2 h = ahalf[a];
            float rx = p.x - q.x, ry = p.y - q.y;
            float dx = rx - fminf(fmaxf(rx, -h.x), h.x);
            float dy = ry - fminf(fmaxf(ry, -h.y), h.y);
            float d2 = fmaf(dx, dx, dy * dy);
            float inv = rsqrtf(fmaxf(d2, EPSF));
            float f = fmaxf(fmaf(rih, inv, -0.5f), 0.0f);
            f = (d2 > EPSF) ? f : 0.0f;
            ax = fmaf(f, dx, ax);
            ay = fmaf(f, dy, ay);
        }
    } else {
        // ------- aabb body -------
        int b  = (g - gc) * 32 + lane;
        int bb = min(b, na - 1);
        const float2 p  = apos[bb];
        const float2 hb = ahalf[bb];

        // aabb vs aabb over flattened idx [lo, min(hi,na))
        int e1 = min(hi, na);
        #pragma unroll 4
        for (int k = lo; k < e1; ++k) {
            float2 q  = apos[k];
            float2 hk = ahalf[k];
            float dax = p.x - q.x, day = p.y - q.y;
            float ovx = (hb.x + hk.x) - fabsf(dax);
            float ovy = (hb.y + hk.y) - fabsf(day);
            bool hit  = (k != bb) & (ovx > 0.0f) & (ovy > 0.0f);
            bool usex = (ovx <= ovy);
            float px = copysignf(0.5f * ovx, dax);
            float py = copysignf(0.5f * ovy, day);
            if (hit) {
                ax += usex ? px : 0.0f;
                ay += usex ? 0.0f : py;
            }
        }

        // aabb vs circle (equal-and-opposite) over idx [max(lo,na), hi)
        int s2 = max(lo, na);
        #pragma unroll 4
        for (int idx = s2; idx < hi; ++idx) {
            int j = idx - na;
            float2 q = cpos[j];
            float rjh = 0.5f * crad[j];
            float rx = q.x - p.x, ry = q.y - p.y;
            float dx = rx - fminf(fmaxf(rx, -hb.x), hb.x);
            float dy = ry - fminf(fmaxf(ry, -hb.y), hb.y);
            float d2 = fmaf(dx, dx, dy * dy);
            float inv = rsqrtf(fmaxf(d2, EPSF));
            float f = fmaxf(fmaf(rjh, inv, -0.5f), 0.0f);
            f = (d2 > EPSF) ? f : 0.0f;
            ax = fmaf(-f, dx, ax);
            ay = fmaf(-f, dy, ay);
        }
    }

    g_part[unit * 32 + lane] = make_float2(ax, ay);
}

__global__ void reduce_kernel(const float2* __restrict__ cpos,
                              const float2* __restrict__ apos,
                              float2* __restrict__ out,
                              int nc, int na, int gc, int C)
{
    int b = blockIdx.x * blockDim.x + threadIdx.x;
    int tot = nc + na;
    if (b >= tot) return;

    int g, lane;
    float2 base;
    if (b < nc) {
        g = b >> 5; lane = b & 31; base = cpos[b];
    } else {
        int a = b - nc;
        g = gc + (a >> 5); lane = a & 31; base = apos[a];
    }

    float sx = base.x, sy = base.y;
    const float2* p = &g_part[(g * C) * 32 + lane];
    #pragma unroll 8
    for (int c = 0; c < C; ++c) {
        float2 v = p[c * 32];
        sx += v.x;
        sy += v.y;
    }
    out[b] = make_float2(sx, sy);
}

extern "C" void kernel_launch(void* const* d_in, const int* in_sizes, int n_in,
                              void* d_out, int out_size)
{
    const float2* cpos  = (const float2*)d_in[0];
    const float*  crad  = (const float*)d_in[1];
    const float2* apos  = (const float2*)d_in[2];
    const float2* ahalf = (const float2*)d_in[3];
    float2* out = (float2*)d_out;

    int nc = in_sizes[1];        // circle_radius element count
    int na = in_sizes[2] / 2;    // aabb_pos has na*2 elements

    int gc = (nc + 31) / 32;
    int ga = (na + 31) / 32;
    int groups = gc + ga;

    int C = TARGET_WARPS / groups;           // 192 -> 37
    if (C < 1) C = 1;
    if (groups * C > 16384) C = 16384 / groups;

    int L = nc + na;
    int len = (L + C - 1) / C;

    int units  = groups * C;
    int grid1  = (units + WPB - 1) / WPB;    // 444 for the nominal shape

    pairs_kernel<<<grid1, 512>>>(cpos, crad, apos, ahalf, nc, na, gc, ga, C, len);

    int tot = nc + na;
    int grid2 = (tot + 255) / 256;
    reduce_kernel<<<grid2, 256>>>(cpos, apos, out, nc, na, gc, C);
}

// round 5
// speedup vs baseline: 1.7915x; 1.1051x over previous
#include <cuda_runtime.h>
#include <cuda_bf16.h>

#define EPSF 1e-9f
#define WPB  16              // warps per block (512 threads)
#define TARGET_WARPS 7104    // 148 SMs * 3 blocks * 16 warps

#define MAX_C 8192
#define MAX_A 8192

// packed bodies: circles (x, y, 0.5*r, 0); boxes (x, y, hx, hy)
__device__ float4 g_circ[MAX_C];
__device__ float4 g_box[MAX_A];
// partial sums: unit index (g*C + c) * 32 + lane
__device__ float2 g_part[16384 * 32];

__global__ void prep_kernel(const float2* __restrict__ cpos,
                            const float*  __restrict__ crad,
                            const float2* __restrict__ apos,
                            const float2* __restrict__ ahalf,
                            int nc, int na)
{
    int i = blockIdx.x * blockDim.x + threadIdx.x;
    if (i < nc) {
        float2 p = cpos[i];
        g_circ[i] = make_float4(p.x, p.y, 0.5f * crad[i], 0.0f);
    }
    if (i < na) {
        float2 p = apos[i];
        float2 h = ahalf[i];
        g_box[i] = make_float4(p.x, p.y, h.x, h.y);
    }
}

__global__ __launch_bounds__(512, 3)
void pairs_kernel(int nc, int na, int gc, int ga, int C, int len)
{
    const int lane = threadIdx.x & 31;
    const int unit = blockIdx.x * WPB + (threadIdx.x >> 5);
    const int groups = gc + ga;
    if (unit >= groups * C) return;

    const int g = unit / C;
    const int c = unit - g * C;
    const int L = nc + na;
    const int lo = c * len;
    const int hi = min(L, lo + len);

    float ax = 0.0f, ay = 0.0f;

    if (g < gc) {
        // ------- circle body -------
        int i  = g * 32 + lane;
        int ii = min(i, nc - 1);
        const float4 p = g_circ[ii];
        const float rih = p.z;

        // circle vs circle: flattened idx [lo, min(hi,nc))
        int e1 = min(hi, nc);
        #pragma unroll 4
        for (int j = lo; j < e1; ++j) {
            float4 q = g_circ[j];
            float dx = p.x - q.x, dy = p.y - q.y;
            float d2 = fmaf(dx, dx, dy * dy);
            float rsh = rih + q.z;
            float inv = rsqrtf(fmaxf(d2, EPSF));
            float f = fmaxf(fmaf(rsh, inv, -0.5f), 0.0f);
            ax = fmaf(f, dx, ax);
            ay = fmaf(f, dy, ay);
        }

        // circle vs aabb: flattened idx [max(lo,nc), hi)
        int s2 = max(lo, nc);
        #pragma unroll 4
        for (int idx = s2; idx < hi; ++idx) {
            float4 q = g_box[idx - nc];
            float rx = p.x - q.x, ry = p.y - q.y;
            float mx = fmaxf(fabsf(rx) - q.z, 0.0f);
            float my = fmaxf(fabsf(ry) - q.w, 0.0f);
            float d2 = fmaf(mx, mx, my * my);
            float inv = rsqrtf(fmaxf(d2, EPSF));
            float f = fmaxf(fmaf(rih, inv, -0.5f), 0.0f);
            ax = fmaf(f, copysignf(mx, rx), ax);
            ay = fmaf(f, copysignf(my, ry), ay);
        }
    } else {
        // ------- aabb body -------
        int b  = (g - gc) * 32 + lane;
        int bb = min(b, na - 1);
        const float4 p = g_box[bb];

        // aabb vs aabb: flattened idx [lo, min(hi,na))
        int e1 = min(hi, na);
        #pragma unroll 4
        for (int k = lo; k < e1; ++k) {
            float4 q = g_box[k];
            float dax = p.x - q.x, day = p.y - q.y;
            float ovx = (p.z + q.z) - fabsf(dax);
            float ovy = (p.w + q.w) - fabsf(day);
            bool hit  = (k != bb) & (ovx > 0.0f) & (ovy > 0.0f);
            bool usex = (ovx <= ovy);
            float px = copysignf(0.5f * ovx, dax);
            float py = copysignf(0.5f * ovy, day);
            ax += (hit & usex)  ? px : 0.0f;
            ay += (hit & !usex) ? py : 0.0f;
        }

        // aabb vs circle (equal-and-opposite): idx [max(lo,na), hi)
        int s2 = max(lo, na);
        #pragma unroll 4
        for (int idx = s2; idx < hi; ++idx) {
            float4 q = g_circ[idx - na];
            float rx = q.x - p.x, ry = q.y - p.y;
            float mx = fmaxf(fabsf(rx) - p.z, 0.0f);
            float my = fmaxf(fabsf(ry) - p.w, 0.0f);
            float d2 = fmaf(mx, mx, my * my);
            float inv = rsqrtf(fmaxf(d2, EPSF));
            float f = fmaxf(fmaf(q.z, inv, -0.5f), 0.0f);
            ax = fmaf(-f, copysignf(mx, rx), ax);
            ay = fmaf(-f, copysignf(my, ry), ay);
        }
    }

    g_part[unit * 32 + lane] = make_float2(ax, ay);
}

template <int CC>
__global__ __launch_bounds__(128)
void reduce_kernel_t(const float2* __restrict__ cpos,
                     const float2* __restrict__ apos,
                     float2* __restrict__ out,
                     int nc, int na, int gc)
{
    int b = blockIdx.x * blockDim.x + threadIdx.x;
    int tot = nc + na;
    if (b >= tot) return;

    int g, lane;
    float2 base;
    if (b < nc) {
        g = b >> 5; lane = b & 31; base = cpos[b];
    } else {
        int a = b - nc;
        g = gc + (a >> 5); lane = a & 31; base = apos[a];
    }

    float sx = base.x, sy = base.y;
    const float2* p = &g_part[(g * CC) * 32 + lane];
    #pragma unroll
    for (int c = 0; c < CC; ++c) {
        float2 v = p[c * 32];
        sx += v.x;
        sy += v.y;
    }
    out[b] = make_float2(sx, sy);
}

__global__ __launch_bounds__(128)
void reduce_kernel_g(const float2* __restrict__ cpos,
                     const float2* __restrict__ apos,
                     float2* __restrict__ out,
                     int nc, int na, int gc, int C)
{
    int b = blockIdx.x * blockDim.x + threadIdx.x;
    int tot = nc + na;
    if (b >= tot) return;

    int g, lane;
    float2 base;
    if (b < nc) {
        g = b >> 5; lane = b & 31; base = cpos[b];
    } else {
        int a = b - nc;
        g = gc + (a >> 5); lane = a & 31; base = apos[a];
    }

    float sx = base.x, sy = base.y;
    const float2* p = &g_part[(g * C) * 32 + lane];
    #pragma unroll 8
    for (int c = 0; c < C; ++c) {
        float2 v = p[c * 32];
        sx += v.x;
        sy += v.y;
    }
    out[b] = make_float2(sx, sy);
}

extern "C" void kernel_launch(void* const* d_in, const int* in_sizes, int n_in,
                              void* d_out, int out_size)
{
    const float2* cpos  = (const float2*)d_in[0];
    const float*  crad  = (const float*)d_in[1];
    const float2* apos  = (const float2*)d_in[2];
    const float2* ahalf = (const float2*)d_in[3];
    float2* out = (float2*)d_out;

    int nc = in_sizes[1];        // circle_radius element count
    int na = in_sizes[2] / 2;    // aabb_pos has na*2 elements

    int gc = (nc + 31) / 32;
    int ga = (na + 31) / 32;
    int groups = gc + ga;

    int C = TARGET_WARPS / groups;           // 192 groups -> 37
    if (C < 1) C = 1;
    if (groups * C > 16384) C = 16384 / groups;

    int L = nc + na;
    int len = (L + C - 1) / C;

    int units = groups * C;
    int grid1 = (units + WPB - 1) / WPB;

    int prep_n = max(nc, na);
    prep_kernel<<<(prep_n + 255) / 256, 256>>>(cpos, crad, apos, ahalf, nc, na);

    pairs_kernel<<<grid1, 512>>>(nc, na, gc, ga, C, len);

    int tot = nc + na;
    int grid2 = (tot + 127) / 128;
    if (C == 37) {
        reduce_kernel_t<37><<<grid2, 128>>>(cpos, apos, out, nc, na, gc);
    } else {
        reduce_kernel_g<<<grid2, 128>>>(cpos, apos, out, nc, na, gc, C);
    }
}

// round 7
// speedup vs baseline: 2.0346x; 1.1357x over previous
#include <cuda_runtime.h>
#include <cuda_bf16.h>

#define EPSF 1e-9f
#define WPB  16              // warps per block (512 threads)
#define TARGET_WARPS 7104    // 148 SMs * 3 blocks * 16 warps
#define MAX_STAGE 352        // max staged bodies per block (2*len)

// partial sums: unit index (c*groups + g) * 32 + lane
__device__ float2 g_part[16384 * 32];

__global__ __launch_bounds__(512, 3)
void pairs_kernel(const float2* __restrict__ cpos,
                  const float*  __restrict__ crad,
                  const float2* __restrict__ apos,
                  const float2* __restrict__ ahalf,
                  int nc, int na, int gc, int groups, int C, int len)
{
    __shared__ float4 s_body[MAX_STAGE];

    const int lane = threadIdx.x & 31;
    const int warp = threadIdx.x >> 5;
    const int unit = blockIdx.x * WPB + warp;
    const int L = nc + na;

    // ---- block-level staging: chunk range shared by (almost) all warps ----
    const int u0 = blockIdx.x * WPB;
    const int c0 = u0 / groups;
    const int lo_blk = c0 * len;
    const int hi_blk = min(L, lo_blk + 2 * len);

    for (int t = lo_blk + threadIdx.x; t < hi_blk; t += 512) {
        float4 v;
        if (t < nc) {
            float2 p = cpos[t];
            v = make_float4(p.x, p.y, 0.5f * crad[t], 0.0f);
        } else {
            float2 p = apos[t - nc];
            float2 h = ahalf[t - nc];
            v = make_float4(p.x, p.y, h.x, h.y);
        }
        s_body[t - lo_blk] = v;
    }
    __syncthreads();

    if (unit >= groups * C) return;

    const int c = unit / groups;
    const int g = unit - c * groups;
    const int lo = c * len;
    const int hi = min(L, lo + len);
    const float4* __restrict__ sb = s_body - lo_blk;   // index by flattened t

    float ax = 0.0f, ay = 0.0f;

    if (g < gc) {
        // ------------- circle body -------------
        int i  = g * 32 + lane;
        int ii = min(i, nc - 1);
        const float2 pp = cpos[ii];
        const float rih = 0.5f * crad[ii];
        const float px = pp.x, py = pp.y;

        // circle vs circle: t in [lo, min(hi,nc))
        int e1 = min(hi, nc);
        #pragma unroll 4
        for (int t = lo; t < e1; ++t) {
            float4 q = sb[t];
            float dx = px - q.x, dy = py - q.y;
            float d2 = fmaf(dx, dx, dy * dy);
            float rsh = rih + q.z;
            float inv = rsqrtf(fmaxf(d2, EPSF));
            float f = fmaxf(fmaf(rsh, inv, -0.5f), 0.0f);
            f = (d2 > EPSF) ? f : 0.0f;
            ax = fmaf(f, dx, ax);
            ay = fmaf(f, dy, ay);
        }

        // circle vs aabb: t in [max(lo,nc), hi)
        int s2 = max(lo, nc);
        #pragma unroll 4
        for (int t = s2; t < hi; ++t) {
            float4 q = sb[t];
            float rx = px - q.x, ry = py - q.y;
            float mx = fmaxf(fabsf(rx) - q.z, 0.0f);
            float my = fmaxf(fabsf(ry) - q.w, 0.0f);
            float d2 = fmaf(mx, mx, my * my);
            float inv = rsqrtf(fmaxf(d2, EPSF));
            float f = fmaxf(fmaf(rih, inv, -0.5f), 0.0f);
            f = (d2 > EPSF) ? f : 0.0f;
            ax = fmaf(f, copysignf(mx, rx), ax);
            ay = fmaf(f, copysignf(my, ry), ay);
        }
    } else {
        // ------------- aabb body -------------
        int b  = (g - gc) * 32 + lane;
        int bb = min(b, na - 1);
        const float2 pp = apos[bb];
        const float2 hh = ahalf[bb];
        const float px = pp.x, py = pp.y;
        const float hx = hh.x, hy = hh.y;
        const int self_t = nc + bb;

        // circle pushes on box (equal-and-opposite): t in [lo, min(hi,nc))
        int e1 = min(hi, nc);
        #pragma unroll 4
        for (int t = lo; t < e1; ++t) {
            float4 q = sb[t];
            float rx = q.x - px, ry = q.y - py;
            float mx = fmaxf(fabsf(rx) - hx, 0.0f);
            float my = fmaxf(fabsf(ry) - hy, 0.0f);
            float d2 = fmaf(mx, mx, my * my);
            float inv = rsqrtf(fmaxf(d2, EPSF));
            float f = fmaxf(fmaf(q.z, inv, -0.5f), 0.0f);
            f = (d2 > EPSF) ? f : 0.0f;
            ax = fmaf(-f, copysignf(mx, rx), ax);
            ay = fmaf(-f, copysignf(my, ry), ay);
        }

        // aabb vs aabb: t in [max(lo,nc), hi)
        int s2 = max(lo, nc);
        #pragma unroll 4
        for (int t = s2; t < hi; ++t) {
            float4 q = sb[t];
            float dax = px - q.x, day = py - q.y;
            float ovx = (hx + q.z) - fabsf(dax);
            float ovy = (hy + q.w) - fabsf(day);
            bool hit  = (t != self_t) & (ovx > 0.0f) & (ovy > 0.0f);
            bool usex = (ovx <= ovy);
            float pxs = copysignf(0.5f * ovx, dax);
            float pys = copysignf(0.5f * ovy, day);
            ax += (hit & usex)  ? pxs : 0.0f;
            ay += (hit & !usex) ? pys : 0.0f;
        }
    }

    g_part[unit * 32 + lane] = make_float2(ax, ay);
}

template <int CC>
__global__ __launch_bounds__(128)
void reduce_kernel_t(const float2* __restrict__ cpos,
                     const float2* __restrict__ apos,
                     float2* __restrict__ out,
                     int nc, int na, int gc, int groups)
{
    int b = blockIdx.x * blockDim.x + threadIdx.x;
    int tot = nc + na;
    if (b >= tot) return;

    int g, lane;
    float2 base;
    if (b < nc) {
        g = b >> 5; lane = b & 31; base = cpos[b];
    } else {
        int a = b - nc;
        g = gc + (a >> 5); lane = a & 31; base = apos[a];
    }

    float sx = base.x, sy = base.y;
    const float2* p = &g_part[g * 32 + lane];
    const int stride = groups * 32;
    #pragma unroll
    for (int c = 0; c < CC; ++c) {
        float2 v = p[c * stride];
        sx += v.x;
        sy += v.y;
    }
    out[b] = make_float2(sx, sy);
}

__global__ __launch_bounds__(128)
void reduce_kernel_g(const float2* __restrict__ cpos,
                     const float2* __restrict__ apos,
                     float2* __restrict__ out,
                     int nc, int na, int gc, int groups, int C)
{
    int b = blockIdx.x * blockDim.x + threadIdx.x;
    int tot = nc + na;
    if (b >= tot) return;

    int g, lane;
    float2 base;
    if (b < nc) {
        g = b >> 5; lane = b & 31; base = cpos[b];
    } else {
        int a = b - nc;
        g = gc + (a >> 5); lane = a & 31; base = apos[a];
    }

    float sx = base.x, sy = base.y;
    const float2* p = &g_part[g * 32 + lane];
    const int stride = groups * 32;
    #pragma unroll 8
    for (int c = 0; c < C; ++c) {
        float2 v = p[c * stride];
        sx += v.x;
        sy += v.y;
    }
    out[b] = make_float2(sx, sy);
}

extern "C" void kernel_launch(void* const* d_in, const int* in_sizes, int n_in,
                              void* d_out, int out_size)
{
    const float2* cpos  = (const float2*)d_in[0];
    const float*  crad  = (const float*)d_in[1];
    const float2* apos  = (const float2*)d_in[2];
    const float2* ahalf = (const float2*)d_in[3];
    float2* out = (float2*)d_out;

    int nc = in_sizes[1];        // circle_radius element count
    int na = in_sizes[2] / 2;    // aabb_pos has na*2 elements

    int gc = (nc + 31) / 32;
    int ga = (na + 31) / 32;
    int groups = gc + ga;
    int L = nc + na;

    int C = TARGET_WARPS / groups;            // 192 groups -> 37
    if (C < 1) C = 1;
    // chunk length must fit the shared staging buffer (2*len <= MAX_STAGE)
    int minC = (L + (MAX_STAGE / 2 - 1)) / (MAX_STAGE / 2);
    if (C < minC) C = minC;
    if (groups * C > 16384) C = 16384 / groups;

    int len = (L + C - 1) / C;

    int units = groups * C;
    int grid1 = (units + WPB - 1) / WPB;

    pairs_kernel<<<grid1, 512>>>(cpos, crad, apos, ahalf,
                                 nc, na, gc, groups, C, len);

    int tot = nc + na;
    int grid2 = (tot + 127) / 128;
    if (C == 37) {
        reduce_kernel_t<37><<<grid2, 128>>>(cpos, apos, out, nc, na, gc, groups);
    } else {
        reduce_kernel_g<<<grid2, 128>>>(cpos, apos, out, nc, na, gc, groups, C);
    }
}